// round 1
// baseline (speedup 1.0000x reference)
#include <cuda_runtime.h>
#include <cstdint>

#define NPTS 40000
#define NSAMP 32
#define STOT (NPTS * NSAMP)     // 1,280,000 sample rows
#define CF 32
#define CIN0 38                 // 3 rel-center + 3 normal + 32 feature
#define C1 64
#define C2 64
#define C3 128
#define BNEPS 1e-5f
#define NWARP 8
#define BLK 256

// ---------------- scratch (device globals; no runtime allocation) ----------
__device__ __align__(16) float g_y0[81920000];   // STOT*64
__device__ __align__(16) float g_y1[81920000];   // STOT*64
__device__ __align__(16) float g_y2[163840000];  // STOT*128

__device__ float g_sum0[C1], g_sq0[C1];
__device__ float g_sum1[C2], g_sq1[C2];
__device__ float g_sum2[C3], g_sq2[C3];
__device__ __align__(16) float g_a0[C1], g_c0[C1];
__device__ __align__(16) float g_a1[C2], g_c1[C2];
__device__ __align__(16) float g_a2[C3], g_c2[C3];

// ---------------- zero the stat accumulators (graph replay safe) -----------
__global__ void k_zero() {
    int t = threadIdx.x;
    if (t < C1) { g_sum0[t] = 0.f; g_sq0[t] = 0.f; g_sum1[t] = 0.f; g_sq1[t] = 0.f; }
    if (t < C3) { g_sum2[t] = 0.f; g_sq2[t] = 0.f; }
}

// ---------------- passthrough copies (center, normal, offset) --------------
__global__ void k_copy(const float* __restrict__ center,
                       const float* __restrict__ normal,
                       const int* __restrict__ offset,
                       float* __restrict__ out, int writeOffsetSlot) {
    int i = blockIdx.x * blockDim.x + threadIdx.x;
    int stride = gridDim.x * blockDim.x;
    for (; i < 2 * NPTS * 3; i += stride) {
        out[i] = (i < NPTS * 3) ? center[i] : normal[i - NPTS * 3];
    }
    if (writeOffsetSlot && blockIdx.x == 0 && threadIdx.x == 0) {
        out[2 * NPTS * 3 + NPTS * C3] = (float)offset[0];
    }
}

// ---------------- layer 0: gather + GEMV(38->64) + stats -------------------
// warp processes 4 samples per chunk; lane owns output channels 2l, 2l+1
__global__ void k_layer0(const float* __restrict__ center,
                         const float* __restrict__ normal,
                         const float* __restrict__ feature,
                         const int* __restrict__ gidx,
                         const float* __restrict__ W0,
                         const float* __restrict__ b0) {
    __shared__ __align__(16) float Wt[CIN0 * C1];     // [c][o]
    __shared__ float xs[NWARP][4][CIN0];
    __shared__ float sStat[2 * C1];

    int tid = threadIdx.x;
    for (int i = tid; i < CIN0 * C1; i += BLK) {
        int o = i / CIN0, c = i % CIN0;
        Wt[c * C1 + o] = W0[i];
    }
    if (tid < 2 * C1) sStat[tid] = 0.f;
    __syncthreads();

    int w = tid >> 5, lane = tid & 31;
    int o0 = 2 * lane;
    float bias0 = b0[o0], bias1 = b0[o0 + 1];
    float ls0 = 0.f, ls1 = 0.f, lq0 = 0.f, lq1 = 0.f;

    int warpGlobal = blockIdx.x * NWARP + w;
    int nWarps = gridDim.x * NWARP;
    const int NCHUNK = STOT / 4;

    for (int chk = warpGlobal; chk < NCHUNK; chk += nWarps) {
        int s0 = chk * 4;
        #pragma unroll
        for (int smp = 0; smp < 4; ++smp) {
            int s = s0 + smp;
            int n = s >> 5;
            int j = gidx[s];
            for (int c = lane; c < CIN0; c += 32) {
                float v;
                if (c < 3)      v = center[j * 3 + c] - center[n * 3 + c];
                else if (c < 6) v = normal[j * 3 + (c - 3)];
                else            v = feature[j * CF + (c - 6)];
                xs[w][smp][c] = v;
            }
        }
        __syncwarp();
        float a00 = bias0, a01 = bias1, a10 = bias0, a11 = bias1;
        float a20 = bias0, a21 = bias1, a30 = bias0, a31 = bias1;
        #pragma unroll
        for (int c = 0; c < CIN0; ++c) {
            float2 wv = *(const float2*)&Wt[c * C1 + o0];
            float x0 = xs[w][0][c], x1 = xs[w][1][c];
            float x2 = xs[w][2][c], x3 = xs[w][3][c];
            a00 += wv.x * x0; a01 += wv.y * x0;
            a10 += wv.x * x1; a11 += wv.y * x1;
            a20 += wv.x * x2; a21 += wv.y * x2;
            a30 += wv.x * x3; a31 += wv.y * x3;
        }
        *(float2*)&g_y0[(size_t)(s0 + 0) * C1 + o0] = make_float2(a00, a01);
        *(float2*)&g_y0[(size_t)(s0 + 1) * C1 + o0] = make_float2(a10, a11);
        *(float2*)&g_y0[(size_t)(s0 + 2) * C1 + o0] = make_float2(a20, a21);
        *(float2*)&g_y0[(size_t)(s0 + 3) * C1 + o0] = make_float2(a30, a31);
        ls0 += a00 + a10 + a20 + a30;
        ls1 += a01 + a11 + a21 + a31;
        lq0 += a00 * a00 + a10 * a10 + a20 * a20 + a30 * a30;
        lq1 += a01 * a01 + a11 * a11 + a21 * a21 + a31 * a31;
        __syncwarp();
    }
    atomicAdd(&sStat[o0], ls0);
    atomicAdd(&sStat[o0 + 1], ls1);
    atomicAdd(&sStat[C1 + o0], lq0);
    atomicAdd(&sStat[C1 + o0 + 1], lq1);
    __syncthreads();
    if (tid < C1) {
        atomicAdd(&g_sum0[tid], sStat[tid]);
        atomicAdd(&g_sq0[tid], sStat[C1 + tid]);
    }
}

__global__ void k_fin0(const float* __restrict__ g, const float* __restrict__ be) {
    int t = threadIdx.x;
    if (t < C1) {
        float inv = 1.f / (float)STOT;
        float mean = g_sum0[t] * inv;
        float var = g_sq0[t] * inv - mean * mean;
        float a = g[t] * rsqrtf(var + BNEPS);
        g_a0[t] = a;
        g_c0[t] = fmaf(-a, mean, be[t]);
    }
}

// ---------------- layer 1: bn0+relu -> GEMV(64->64) + stats ----------------
__global__ void k_layer1(const float* __restrict__ W1, const float* __restrict__ b1) {
    __shared__ __align__(16) float Wt[C1 * C2];       // [c][o] 16 KB
    __shared__ __align__(16) float xs[NWARP][4][C1];  // 8 KB
    __shared__ float sStat[2 * C2];

    int tid = threadIdx.x;
    for (int i = tid; i < C1 * C2; i += BLK) {
        int o = i / C1, c = i % C1;
        Wt[c * C2 + o] = W1[i];
    }
    if (tid < 2 * C2) sStat[tid] = 0.f;
    __syncthreads();

    int w = tid >> 5, lane = tid & 31;
    int o0 = 2 * lane;
    float bias0 = b1[o0], bias1 = b1[o0 + 1];
    float av0 = g_a0[o0], cv0 = g_c0[o0];
    float av1 = g_a0[o0 + 1], cv1 = g_c0[o0 + 1];
    float ls0 = 0.f, ls1 = 0.f, lq0 = 0.f, lq1 = 0.f;

    int warpGlobal = blockIdx.x * NWARP + w;
    int nWarps = gridDim.x * NWARP;
    const int NCHUNK = STOT / 4;

    for (int chk = warpGlobal; chk < NCHUNK; chk += nWarps) {
        int s0 = chk * 4;
        #pragma unroll
        for (int smp = 0; smp < 4; ++smp) {
            int s = s0 + smp;
            float2 y = *(const float2*)&g_y0[(size_t)s * C1 + o0];
            float2 xv;
            xv.x = fmaxf(0.f, fmaf(av0, y.x, cv0));
            xv.y = fmaxf(0.f, fmaf(av1, y.y, cv1));
            *(float2*)&xs[w][smp][o0] = xv;
        }
        __syncwarp();
        float a00 = bias0, a01 = bias1, a10 = bias0, a11 = bias1;
        float a20 = bias0, a21 = bias1, a30 = bias0, a31 = bias1;
        #pragma unroll 16
        for (int c = 0; c < C1; ++c) {
            float2 wv = *(const float2*)&Wt[c * C2 + o0];
            float x0 = xs[w][0][c], x1 = xs[w][1][c];
            float x2 = xs[w][2][c], x3 = xs[w][3][c];
            a00 += wv.x * x0; a01 += wv.y * x0;
            a10 += wv.x * x1; a11 += wv.y * x1;
            a20 += wv.x * x2; a21 += wv.y * x2;
            a30 += wv.x * x3; a31 += wv.y * x3;
        }
        *(float2*)&g_y1[(size_t)(s0 + 0) * C2 + o0] = make_float2(a00, a01);
        *(float2*)&g_y1[(size_t)(s0 + 1) * C2 + o0] = make_float2(a10, a11);
        *(float2*)&g_y1[(size_t)(s0 + 2) * C2 + o0] = make_float2(a20, a21);
        *(float2*)&g_y1[(size_t)(s0 + 3) * C2 + o0] = make_float2(a30, a31);
        ls0 += a00 + a10 + a20 + a30;
        ls1 += a01 + a11 + a21 + a31;
        lq0 += a00 * a00 + a10 * a10 + a20 * a20 + a30 * a30;
        lq1 += a01 * a01 + a11 * a11 + a21 * a21 + a31 * a31;
        __syncwarp();
    }
    atomicAdd(&sStat[o0], ls0);
    atomicAdd(&sStat[o0 + 1], ls1);
    atomicAdd(&sStat[C2 + o0], lq0);
    atomicAdd(&sStat[C2 + o0 + 1], lq1);
    __syncthreads();
    if (tid < C2) {
        atomicAdd(&g_sum1[tid], sStat[tid]);
        atomicAdd(&g_sq1[tid], sStat[C2 + tid]);
    }
}

__global__ void k_fin1(const float* __restrict__ g, const float* __restrict__ be) {
    int t = threadIdx.x;
    if (t < C2) {
        float inv = 1.f / (float)STOT;
        float mean = g_sum1[t] * inv;
        float var = g_sq1[t] * inv - mean * mean;
        float a = g[t] * rsqrtf(var + BNEPS);
        g_a1[t] = a;
        g_c1[t] = fmaf(-a, mean, be[t]);
    }
}

// ---------------- layer 2: bn1+relu -> GEMV(64->128) + stats ---------------
// lane owns output channels 4l..4l+3 (float4 W loads)
__global__ void k_layer2(const float* __restrict__ W2, const float* __restrict__ b2) {
    __shared__ __align__(16) float Wt[C2 * C3];       // [c][o] 32 KB
    __shared__ __align__(16) float xs[NWARP][4][C2];  // 8 KB
    __shared__ float sStat[2 * C3];

    int tid = threadIdx.x;
    for (int i = tid; i < C2 * C3; i += BLK) {
        int o = i / C2, c = i % C2;
        Wt[c * C3 + o] = W2[i];
    }
    if (tid < 2 * C3) sStat[tid] = 0.f;
    __syncthreads();

    int w = tid >> 5, lane = tid & 31;
    int o0 = 4 * lane;     // output channels o0..o0+3
    int i0 = 2 * lane;     // input channels this lane stages
    float4 bias = *(const float4*)&b2[o0];
    float av0 = g_a1[i0], cv0 = g_c1[i0];
    float av1 = g_a1[i0 + 1], cv1 = g_c1[i0 + 1];
    float ls[4] = {0.f, 0.f, 0.f, 0.f};
    float lq[4] = {0.f, 0.f, 0.f, 0.f};

    int warpGlobal = blockIdx.x * NWARP + w;
    int nWarps = gridDim.x * NWARP;
    const int NCHUNK = STOT / 4;

    for (int chk = warpGlobal; chk < NCHUNK; chk += nWarps) {
        int s0 = chk * 4;
        #pragma unroll
        for (int smp = 0; smp < 4; ++smp) {
            int s = s0 + smp;
            float2 y = *(const float2*)&g_y1[(size_t)s * C2 + i0];
            float2 xv;
            xv.x = fmaxf(0.f, fmaf(av0, y.x, cv0));
            xv.y = fmaxf(0.f, fmaf(av1, y.y, cv1));
            *(float2*)&xs[w][smp][i0] = xv;
        }
        __syncwarp();
        float acc[4][4];
        #pragma unroll
        for (int smp = 0; smp < 4; ++smp) {
            acc[smp][0] = bias.x; acc[smp][1] = bias.y;
            acc[smp][2] = bias.z; acc[smp][3] = bias.w;
        }
        #pragma unroll 8
        for (int c = 0; c < C2; ++c) {
            float4 wv = *(const float4*)&Wt[c * C3 + o0];
            float x0 = xs[w][0][c], x1 = xs[w][1][c];
            float x2 = xs[w][2][c], x3 = xs[w][3][c];
            acc[0][0] += wv.x * x0; acc[0][1] += wv.y * x0;
            acc[0][2] += wv.z * x0; acc[0][3] += wv.w * x0;
            acc[1][0] += wv.x * x1; acc[1][1] += wv.y * x1;
            acc[1][2] += wv.z * x1; acc[1][3] += wv.w * x1;
            acc[2][0] += wv.x * x2; acc[2][1] += wv.y * x2;
            acc[2][2] += wv.z * x2; acc[2][3] += wv.w * x2;
            acc[3][0] += wv.x * x3; acc[3][1] += wv.y * x3;
            acc[3][2] += wv.z * x3; acc[3][3] += wv.w * x3;
        }
        #pragma unroll
        for (int smp = 0; smp < 4; ++smp) {
            *(float4*)&g_y2[(size_t)(s0 + smp) * C3 + o0] =
                make_float4(acc[smp][0], acc[smp][1], acc[smp][2], acc[smp][3]);
            #pragma unroll
            for (int q = 0; q < 4; ++q) {
                ls[q] += acc[smp][q];
                lq[q] += acc[smp][q] * acc[smp][q];
            }
        }
        __syncwarp();
    }
    #pragma unroll
    for (int q = 0; q < 4; ++q) {
        atomicAdd(&sStat[o0 + q], ls[q]);
        atomicAdd(&sStat[C3 + o0 + q], lq[q]);
    }
    __syncthreads();
    if (tid < C3) {
        atomicAdd(&g_sum2[tid], sStat[tid]);
        atomicAdd(&g_sq2[tid], sStat[C3 + tid]);
    }
}

__global__ void k_fin2(const float* __restrict__ g, const float* __restrict__ be) {
    int t = threadIdx.x;
    if (t < C3) {
        float inv = 1.f / (float)STOT;
        float mean = g_sum2[t] * inv;
        float var = g_sq2[t] * inv - mean * mean;
        float a = g[t] * rsqrtf(var + BNEPS);
        g_a2[t] = a;
        g_c2[t] = fmaf(-a, mean, be[t]);
    }
}

// ---------------- final: bn2+relu+max over NS ------------------------------
__global__ void k_pool(float* __restrict__ out) {
    int tid = threadIdx.x;
    int w = tid >> 5, lane = tid & 31;
    int o0 = 4 * lane;
    float4 a = *(const float4*)&g_a2[o0];
    float4 cc = *(const float4*)&g_c2[o0];

    int warpGlobal = blockIdx.x * NWARP + w;
    int nWarps = gridDim.x * NWARP;

    for (int n = warpGlobal; n < NPTS; n += nWarps) {
        float4 m = make_float4(0.f, 0.f, 0.f, 0.f);  // relu floor
        #pragma unroll 8
        for (int s = 0; s < NSAMP; ++s) {
            float4 y = *(const float4*)&g_y2[((size_t)n * NSAMP + s) * C3 + o0];
            m.x = fmaxf(m.x, fmaf(a.x, y.x, cc.x));
            m.y = fmaxf(m.y, fmaf(a.y, y.y, cc.y));
            m.z = fmaxf(m.z, fmaf(a.z, y.z, cc.z));
            m.w = fmaxf(m.w, fmaf(a.w, y.w, cc.w));
        }
        *(float4*)&out[(size_t)n * C3 + o0] = m;
    }
}

// ---------------- host entry ------------------------------------------------
extern "C" void kernel_launch(void* const* d_in, const int* in_sizes, int n_in,
                              void* d_out, int out_size) {
    const float* center  = (const float*)d_in[0];
    const float* normal  = (const float*)d_in[1];
    const float* feature = (const float*)d_in[2];
    const int*   offset  = (const int*)d_in[3];
    const int*   gidx    = (const int*)d_in[4];
    const float* W0 = (const float*)d_in[5];
    const float* b0 = (const float*)d_in[6];
    const float* g0 = (const float*)d_in[7];
    const float* be0 = (const float*)d_in[8];
    const float* W1 = (const float*)d_in[9];
    const float* b1 = (const float*)d_in[10];
    const float* g1 = (const float*)d_in[11];
    const float* be1 = (const float*)d_in[12];
    const float* W2 = (const float*)d_in[13];
    const float* b2 = (const float*)d_in[14];
    const float* g2 = (const float*)d_in[15];
    const float* be2 = (const float*)d_in[16];

    float* out = (float*)d_out;

    // Output layout hedge: full tuple (center|normal|out|offset) vs out-only.
    bool full = (out_size >= 2 * NPTS * 3 + NPTS * C3 + 1);
    float* featBase = full ? out + 2 * NPTS * 3 : out;

    k_zero<<<1, 128>>>();
    if (full) k_copy<<<256, 256>>>(center, normal, offset, out, 1);

    const int GRID = 1184;  // 148 SMs * 8
    k_layer0<<<GRID, BLK>>>(center, normal, feature, gidx, W0, b0);
    k_fin0<<<1, 64>>>(g0, be0);
    k_layer1<<<GRID, BLK>>>(W1, b1);
    k_fin1<<<1, 64>>>(g1, be1);
    k_layer2<<<GRID, BLK>>>(W2, b2);
    k_fin2<<<1, 128>>>(g2, be2);
    k_pool<<<592, BLK>>>(featBase);
}

// round 2
// speedup vs baseline: 1.3777x; 1.3777x over previous
#include <cuda_runtime.h>
#include <mma.h>
#include <cstdint>

using namespace nvcuda;

#define NPTS 40000
#define NSAMP 32
#define STOT (NPTS * NSAMP)     // 1,280,000
#define C0IN 38
#define C1 64
#define C2 64
#define C3 128
#define BNEPS 1e-5f
#define BLK 256
#define NWARP 8
#define NTILE (STOT / 128)      // 10000 M-tiles of 128 samples (= 4 points)
#define LDX 72                  // staging tile leading dim (floats)
#define LDW1 72
#define LDW2 136
#define LDY2 132

// ---------------- scratch (device globals) ---------------------------------
__device__ __align__(16) float g_A[NPTS * C1];     // per-point A = W0*x_n + b0
__device__ __align__(16) float g_B[NPTS * C1];     // per-point B = W0c*center_n
__device__ __align__(16) float g_y1[(size_t)STOT * C2];   // 327 MB
__device__ __align__(16) float g_pmax[NPTS * C3];
__device__ __align__(16) float g_pmin[NPTS * C3];

__device__ float g_sum0[C1], g_sq0[C1];
__device__ float g_sum1[C2], g_sq1[C2];
__device__ float g_sum2[C3], g_sq2[C3];
__device__ __align__(16) float g_a0[C1], g_c0[C1];
__device__ __align__(16) float g_a1[C2], g_c1[C2];
__device__ __align__(16) float g_a2[C3], g_c2[C3];

// ---------------- zero stat accumulators (replay safe) ---------------------
__global__ void k_zero() {
    int t = threadIdx.x;
    if (t < C1) { g_sum0[t] = 0.f; g_sq0[t] = 0.f; g_sum1[t] = 0.f; g_sq1[t] = 0.f; }
    if (t < C3) { g_sum2[t] = 0.f; g_sq2[t] = 0.f; }
}

// ---------------- passthrough (center|normal|offset) -----------------------
__global__ void k_copy(const float* __restrict__ center,
                       const float* __restrict__ normal,
                       const int* __restrict__ offset,
                       float* __restrict__ out, int writeOffsetSlot) {
    int i = blockIdx.x * blockDim.x + threadIdx.x;
    int stride = gridDim.x * blockDim.x;
    for (; i < 2 * NPTS * 3; i += stride) {
        out[i] = (i < NPTS * 3) ? center[i] : normal[i - NPTS * 3];
    }
    if (writeOffsetSlot && blockIdx.x == 0 && threadIdx.x == 0) {
        out[2 * NPTS * 3 + NPTS * C3] = (float)offset[0];
    }
}

// ---------------- per-point precompute A, B --------------------------------
__global__ void k_pre(const float* __restrict__ center,
                      const float* __restrict__ normal,
                      const float* __restrict__ feature,
                      const float* __restrict__ W0,
                      const float* __restrict__ b0) {
    __shared__ __align__(16) float Wt[C0IN * C1];   // [c][o]
    __shared__ float xs[NWARP][C0IN];
    int tid = threadIdx.x;
    for (int i = tid; i < C0IN * C1; i += BLK) {
        int o = i / C0IN, c = i % C0IN;
        Wt[c * C1 + o] = W0[i];
    }
    __syncthreads();
    int w = tid >> 5, lane = tid & 31;
    int o0 = 2 * lane;
    float bias0 = b0[o0], bias1 = b0[o0 + 1];
    int wg = blockIdx.x * NWARP + w, nW = gridDim.x * NWARP;
    for (int n = wg; n < NPTS; n += nW) {
        {
            float v;
            if (lane < 3)      v = center[n * 3 + lane];
            else if (lane < 6) v = normal[n * 3 + lane - 3];
            else               v = feature[n * 32 + lane - 6];
            xs[w][lane] = v;
            if (lane < C0IN - 32) xs[w][32 + lane] = feature[n * 32 + 26 + lane];
        }
        __syncwarp();
        float a0 = 0.f, a1 = 0.f, bp0 = 0.f, bp1 = 0.f;
        #pragma unroll
        for (int c = 0; c < C0IN; ++c) {
            float2 wv = *(const float2*)&Wt[c * C1 + o0];
            float x = xs[w][c];
            a0 += wv.x * x; a1 += wv.y * x;
            if (c < 3) { bp0 += wv.x * x; bp1 += wv.y * x; }
        }
        *(float2*)&g_A[n * C1 + o0] = make_float2(a0 + bias0, a1 + bias1);
        *(float2*)&g_B[n * C1 + o0] = make_float2(bp0, bp1);
        __syncwarp();
    }
}

// ---------------- layer-0 stats: y0 = A[j]-B[n] ----------------------------
__global__ void k_l0stats(const int* __restrict__ gidx) {
    __shared__ float sS[C1], sQ[C1];
    int tid = threadIdx.x;
    if (tid < C1) { sS[tid] = 0.f; sQ[tid] = 0.f; }
    __syncthreads();
    int w = tid >> 5, lane = tid & 31, c0 = 2 * lane;
    float s0 = 0.f, s1 = 0.f, q0 = 0.f, q1 = 0.f;
    int wg = blockIdx.x * NWARP + w, nW = gridDim.x * NWARP;
    for (int n = wg; n < NPTS; n += nW) {
        float2 bv = *(const float2*)&g_B[n * C1 + c0];
        int js = gidx[n * NSAMP + lane];
        #pragma unroll
        for (int s = 0; s < NSAMP; ++s) {
            int j = __shfl_sync(0xffffffffu, js, s);
            float2 av = *(const float2*)&g_A[j * C1 + c0];
            float y0 = av.x - bv.x, y1v = av.y - bv.y;
            s0 += y0; s1 += y1v; q0 += y0 * y0; q1 += y1v * y1v;
        }
    }
    atomicAdd(&sS[c0], s0); atomicAdd(&sS[c0 + 1], s1);
    atomicAdd(&sQ[c0], q0); atomicAdd(&sQ[c0 + 1], q1);
    __syncthreads();
    if (tid < C1) { atomicAdd(&g_sum0[tid], sS[tid]); atomicAdd(&g_sq0[tid], sQ[tid]); }
}

__global__ void k_fin0(const float* __restrict__ g, const float* __restrict__ be) {
    int t = threadIdx.x;
    if (t < C1) {
        float inv = 1.f / (float)STOT;
        float mean = g_sum0[t] * inv;
        float var = g_sq0[t] * inv - mean * mean;
        float a = g[t] * rsqrtf(var + BNEPS);
        g_a0[t] = a;
        g_c0[t] = fmaf(-a, mean, be[t]);
    }
}
__global__ void k_fin1(const float* __restrict__ g, const float* __restrict__ be) {
    int t = threadIdx.x;
    if (t < C2) {
        float inv = 1.f / (float)STOT;
        float mean = g_sum1[t] * inv;
        float var = g_sq1[t] * inv - mean * mean;
        float a = g[t] * rsqrtf(var + BNEPS);
        g_a1[t] = a;
        g_c1[t] = fmaf(-a, mean, be[t]);
    }
}
__global__ void k_fin2(const float* __restrict__ g, const float* __restrict__ be) {
    int t = threadIdx.x;
    if (t < C3) {
        float inv = 1.f / (float)STOT;
        float mean = g_sum2[t] * inv;
        float var = g_sq2[t] * inv - mean * mean;
        float a = g[t] * rsqrtf(var + BNEPS);
        g_a2[t] = a;
        g_c2[t] = fmaf(-a, mean, be[t]);
    }
}

// ---------------- layer 1: recompute y0 -> BN0+relu -> TF32 GEMM 64->64 ----
__global__ void __launch_bounds__(BLK) k_layer1(const int* __restrict__ gidx,
                                                const float* __restrict__ W1,
                                                const float* __restrict__ b1) {
    extern __shared__ float sm[];
    float* xs = sm;                   // [128][LDX] x-tile, reused as y-tile
    float* Ws = sm + 128 * LDX;       // [C1][LDW1]
    __shared__ float aS[C1], cS[C1];
    __shared__ float sS[C2], sQ[C2];
    int tid = threadIdx.x;
    for (int i = tid; i < C1 * C2; i += BLK) {
        int o = i / C1, c = i % C1;
        Ws[c * LDW1 + o] = wmma::__float_to_tf32(W1[i]);
    }
    if (tid < C1) { aS[tid] = g_a0[tid]; cS[tid] = g_c0[tid]; sS[tid] = 0.f; sQ[tid] = 0.f; }
    __syncthreads();

    int w = tid >> 5;
    int wm = w >> 1, wn = w & 1;          // warp tile: rows wm*32..+31, cols wn*32..+31
    int col4 = (tid & 15) * 4, rg = tid >> 4;  // output mapping: 16x16 grid
    float4 bv = *(const float4*)&b1[col4];
    float4 sum4 = make_float4(0, 0, 0, 0), sq4 = make_float4(0, 0, 0, 0);

    for (int t = blockIdx.x; t < NTILE; t += gridDim.x) {
        int s0 = t * 128;
        // stage x-tile: x = relu(a0*(A[j]-B[n]) + c0), tf32
        for (int idx = tid; idx < 128 * 16; idx += BLK) {
            int r = idx >> 4; int cg = (idx & 15) * 4;
            int s = s0 + r; int j = gidx[s]; int n = s >> 5;
            float4 av = *(const float4*)&g_A[j * C1 + cg];
            float4 b4 = *(const float4*)&g_B[n * C1 + cg];
            xs[r * LDX + cg + 0] = wmma::__float_to_tf32(fmaxf(0.f, fmaf(aS[cg + 0], av.x - b4.x, cS[cg + 0])));
            xs[r * LDX + cg + 1] = wmma::__float_to_tf32(fmaxf(0.f, fmaf(aS[cg + 1], av.y - b4.y, cS[cg + 1])));
            xs[r * LDX + cg + 2] = wmma::__float_to_tf32(fmaxf(0.f, fmaf(aS[cg + 2], av.z - b4.z, cS[cg + 2])));
            xs[r * LDX + cg + 3] = wmma::__float_to_tf32(fmaxf(0.f, fmaf(aS[cg + 3], av.w - b4.w, cS[cg + 3])));
        }
        __syncthreads();

        wmma::fragment<wmma::accumulator, 16, 16, 8, float> acc[2][2];
        #pragma unroll
        for (int i = 0; i < 2; ++i)
            #pragma unroll
            for (int jj = 0; jj < 2; ++jj) wmma::fill_fragment(acc[i][jj], 0.f);
        #pragma unroll
        for (int k = 0; k < C1; k += 8) {
            wmma::fragment<wmma::matrix_a, 16, 16, 8, wmma::precision::tf32, wmma::row_major> fa0, fa1;
            wmma::fragment<wmma::matrix_b, 16, 16, 8, wmma::precision::tf32, wmma::row_major> fb0, fb1;
            wmma::load_matrix_sync(fa0, xs + (wm * 32 + 0) * LDX + k, LDX);
            wmma::load_matrix_sync(fa1, xs + (wm * 32 + 16) * LDX + k, LDX);
            wmma::load_matrix_sync(fb0, Ws + k * LDW1 + wn * 32 + 0, LDW1);
            wmma::load_matrix_sync(fb1, Ws + k * LDW1 + wn * 32 + 16, LDW1);
            wmma::mma_sync(acc[0][0], fa0, fb0, acc[0][0]);
            wmma::mma_sync(acc[0][1], fa0, fb1, acc[0][1]);
            wmma::mma_sync(acc[1][0], fa1, fb0, acc[1][0]);
            wmma::mma_sync(acc[1][1], fa1, fb1, acc[1][1]);
        }
        __syncthreads();
        #pragma unroll
        for (int i = 0; i < 2; ++i)
            #pragma unroll
            for (int jj = 0; jj < 2; ++jj)
                wmma::store_matrix_sync(xs + (wm * 32 + i * 16) * LDX + wn * 32 + jj * 16,
                                        acc[i][jj], LDX, wmma::mem_row_major);
        __syncthreads();
        // output: add bias, write y1, accumulate stats
        #pragma unroll
        for (int r8 = 0; r8 < 8; ++r8) {
            int r = rg * 8 + r8;
            float4 v = *(float4*)&xs[r * LDX + col4];
            v.x += bv.x; v.y += bv.y; v.z += bv.z; v.w += bv.w;
            *(float4*)&g_y1[(size_t)(s0 + r) * C2 + col4] = v;
            sum4.x += v.x; sum4.y += v.y; sum4.z += v.z; sum4.w += v.w;
            sq4.x += v.x * v.x; sq4.y += v.y * v.y; sq4.z += v.z * v.z; sq4.w += v.w * v.w;
        }
        __syncthreads();
    }
    atomicAdd(&sS[col4 + 0], sum4.x); atomicAdd(&sS[col4 + 1], sum4.y);
    atomicAdd(&sS[col4 + 2], sum4.z); atomicAdd(&sS[col4 + 3], sum4.w);
    atomicAdd(&sQ[col4 + 0], sq4.x);  atomicAdd(&sQ[col4 + 1], sq4.y);
    atomicAdd(&sQ[col4 + 2], sq4.z);  atomicAdd(&sQ[col4 + 3], sq4.w);
    __syncthreads();
    if (tid < C2) { atomicAdd(&g_sum1[tid], sS[tid]); atomicAdd(&g_sq1[tid], sQ[tid]); }
}

// ---------------- layer 2: BN1+relu -> TF32 GEMM 64->128 + fused pool ------
__global__ void __launch_bounds__(BLK) k_layer2(const float* __restrict__ W2,
                                                const float* __restrict__ b2) {
    extern __shared__ float sm[];
    float* xs = sm;                   // [128][LDX] staging; reused as y-half [64][LDY2]
    float* Ws = sm + 128 * LDX;       // [C2][LDW2]
    __shared__ float aS[C2], cS[C2];
    __shared__ float sS[C3], sQ[C3];
    __shared__ __align__(16) float sMx[8][C3];
    __shared__ __align__(16) float sMn[8][C3];
    int tid = threadIdx.x;
    for (int i = tid; i < C2 * C3; i += BLK) {
        int o = i / C2, c = i % C2;
        Ws[c * LDW2 + o] = wmma::__float_to_tf32(W2[i]);
    }
    if (tid < C2) { aS[tid] = g_a1[tid]; cS[tid] = g_c1[tid]; }
    if (tid < C3) { sS[tid] = 0.f; sQ[tid] = 0.f; }
    __syncthreads();

    int w = tid >> 5;
    int wm = w >> 1, wn = w & 1;              // warp tile: rows wm*32..+31, cols wn*64..+63
    int col4 = (tid & 31) * 4, rg = tid >> 5; // output mapping: rg 0..7, 32 col-groups
    float4 bv = *(const float4*)&b2[col4];
    float4 sum4 = make_float4(0, 0, 0, 0), sq4 = make_float4(0, 0, 0, 0);

    for (int t = blockIdx.x; t < NTILE; t += gridDim.x) {
        int s0 = t * 128;
        for (int idx = tid; idx < 128 * 16; idx += BLK) {
            int r = idx >> 4; int cg = (idx & 15) * 4;
            float4 y = *(const float4*)&g_y1[(size_t)(s0 + r) * C2 + cg];
            xs[r * LDX + cg + 0] = wmma::__float_to_tf32(fmaxf(0.f, fmaf(aS[cg + 0], y.x, cS[cg + 0])));
            xs[r * LDX + cg + 1] = wmma::__float_to_tf32(fmaxf(0.f, fmaf(aS[cg + 1], y.y, cS[cg + 1])));
            xs[r * LDX + cg + 2] = wmma::__float_to_tf32(fmaxf(0.f, fmaf(aS[cg + 2], y.z, cS[cg + 2])));
            xs[r * LDX + cg + 3] = wmma::__float_to_tf32(fmaxf(0.f, fmaf(aS[cg + 3], y.w, cS[cg + 3])));
        }
        __syncthreads();

        wmma::fragment<wmma::accumulator, 16, 16, 8, float> acc[2][4];
        #pragma unroll
        for (int i = 0; i < 2; ++i)
            #pragma unroll
            for (int jj = 0; jj < 4; ++jj) wmma::fill_fragment(acc[i][jj], 0.f);
        #pragma unroll
        for (int k = 0; k < C2; k += 8) {
            wmma::fragment<wmma::matrix_a, 16, 16, 8, wmma::precision::tf32, wmma::row_major> fa0, fa1;
            wmma::load_matrix_sync(fa0, xs + (wm * 32 + 0) * LDX + k, LDX);
            wmma::load_matrix_sync(fa1, xs + (wm * 32 + 16) * LDX + k, LDX);
            #pragma unroll
            for (int jj = 0; jj < 4; ++jj) {
                wmma::fragment<wmma::matrix_b, 16, 16, 8, wmma::precision::tf32, wmma::row_major> fb;
                wmma::load_matrix_sync(fb, Ws + k * LDW2 + wn * 64 + jj * 16, LDW2);
                wmma::mma_sync(acc[0][jj], fa0, fb, acc[0][jj]);
                wmma::mma_sync(acc[1][jj], fa1, fb, acc[1][jj]);
            }
        }
        __syncthreads();

        // two half-tiles of 64 rows (= 2 points each)
        #pragma unroll
        for (int h = 0; h < 2; ++h) {
            if ((wm >> 1) == h) {
                int rbase = (wm & 1) * 32;
                #pragma unroll
                for (int i = 0; i < 2; ++i)
                    #pragma unroll
                    for (int jj = 0; jj < 4; ++jj)
                        wmma::store_matrix_sync(xs + (rbase + i * 16) * LDY2 + wn * 64 + jj * 16,
                                                acc[i][jj], LDY2, wmma::mem_row_major);
            }
            __syncthreads();
            float4 mx = make_float4(-1e30f, -1e30f, -1e30f, -1e30f);
            float4 mn = make_float4(1e30f, 1e30f, 1e30f, 1e30f);
            #pragma unroll
            for (int r8 = 0; r8 < 8; ++r8) {
                int r = rg * 8 + r8;
                float4 v = *(float4*)&xs[r * LDY2 + col4];
                v.x += bv.x; v.y += bv.y; v.z += bv.z; v.w += bv.w;
                sum4.x += v.x; sum4.y += v.y; sum4.z += v.z; sum4.w += v.w;
                sq4.x += v.x * v.x; sq4.y += v.y * v.y; sq4.z += v.z * v.z; sq4.w += v.w * v.w;
                mx.x = fmaxf(mx.x, v.x); mx.y = fmaxf(mx.y, v.y);
                mx.z = fmaxf(mx.z, v.z); mx.w = fmaxf(mx.w, v.w);
                mn.x = fminf(mn.x, v.x); mn.y = fminf(mn.y, v.y);
                mn.z = fminf(mn.z, v.z); mn.w = fminf(mn.w, v.w);
            }
            *(float4*)&sMx[rg][col4] = mx;
            *(float4*)&sMn[rg][col4] = mn;
            __syncthreads();
            {
                int pih = tid >> 7, col = tid & 127;
                float m0 = fmaxf(fmaxf(sMx[pih * 4 + 0][col], sMx[pih * 4 + 1][col]),
                                 fmaxf(sMx[pih * 4 + 2][col], sMx[pih * 4 + 3][col]));
                float m1 = fminf(fminf(sMn[pih * 4 + 0][col], sMn[pih * 4 + 1][col]),
                                 fminf(sMn[pih * 4 + 2][col], sMn[pih * 4 + 3][col]));
                int n = t * 4 + h * 2 + pih;
                g_pmax[n * C3 + col] = m0;
                g_pmin[n * C3 + col] = m1;
            }
            __syncthreads();
        }
    }
    atomicAdd(&sS[col4 + 0], sum4.x); atomicAdd(&sS[col4 + 1], sum4.y);
    atomicAdd(&sS[col4 + 2], sum4.z); atomicAdd(&sS[col4 + 3], sum4.w);
    atomicAdd(&sQ[col4 + 0], sq4.x);  atomicAdd(&sQ[col4 + 1], sq4.y);
    atomicAdd(&sQ[col4 + 2], sq4.z);  atomicAdd(&sQ[col4 + 3], sq4.w);
    __syncthreads();
    if (tid < C3) { atomicAdd(&g_sum2[tid], sS[tid]); atomicAdd(&g_sq2[tid], sQ[tid]); }
}

// ---------------- epilogue: BN2+relu on pooled extrema ---------------------
__global__ void k_poolapply(float* __restrict__ out) {
    int idx = blockIdx.x * blockDim.x + threadIdx.x;
    if (idx >= NPTS * (C3 / 4)) return;
    int n = idx >> 5, cg = (idx & 31) * 4;
    float4 a = *(const float4*)&g_a2[cg];
    float4 c = *(const float4*)&g_c2[cg];
    float4 mx = *(const float4*)&g_pmax[n * C3 + cg];
    float4 mn = *(const float4*)&g_pmin[n * C3 + cg];
    float4 o;
    o.x = fmaxf(0.f, fmaf(a.x, (a.x > 0.f) ? mx.x : mn.x, c.x));
    o.y = fmaxf(0.f, fmaf(a.y, (a.y > 0.f) ? mx.y : mn.y, c.y));
    o.z = fmaxf(0.f, fmaf(a.z, (a.z > 0.f) ? mx.z : mn.z, c.z));
    o.w = fmaxf(0.f, fmaf(a.w, (a.w > 0.f) ? mx.w : mn.w, c.w));
    *(float4*)&out[(size_t)n * C3 + cg] = o;
}

// ---------------- host entry ------------------------------------------------
extern "C" void kernel_launch(void* const* d_in, const int* in_sizes, int n_in,
                              void* d_out, int out_size) {
    const float* center  = (const float*)d_in[0];
    const float* normal  = (const float*)d_in[1];
    const float* feature = (const float*)d_in[2];
    const int*   offset  = (const int*)d_in[3];
    const int*   gidx    = (const int*)d_in[4];
    const float* W0 = (const float*)d_in[5];
    const float* b0 = (const float*)d_in[6];
    const float* g0 = (const float*)d_in[7];
    const float* be0 = (const float*)d_in[8];
    const float* W1 = (const float*)d_in[9];
    const float* b1 = (const float*)d_in[10];
    const float* g1 = (const float*)d_in[11];
    const float* be1 = (const float*)d_in[12];
    const float* W2 = (const float*)d_in[13];
    const float* b2 = (const float*)d_in[14];
    const float* g2 = (const float*)d_in[15];
    const float* be2 = (const float*)d_in[16];

    float* out = (float*)d_out;
    bool full = (out_size >= 2 * NPTS * 3 + NPTS * C3 + 1);
    float* featBase = full ? out + 2 * NPTS * 3 : out;

    const int SM1 = (128 * LDX + C1 * LDW1) * 4;   // 55296 B
    const int SM2 = (128 * LDX + C2 * LDW2) * 4;   // 71680 B
    cudaFuncSetAttribute(k_layer1, cudaFuncAttributeMaxDynamicSharedMemorySize, SM1);
    cudaFuncSetAttribute(k_layer2, cudaFuncAttributeMaxDynamicSharedMemorySize, SM2);

    k_zero<<<1, 128>>>();
    if (full) k_copy<<<256, 256>>>(center, normal, offset, out, 1);

    k_pre<<<160, BLK>>>(center, normal, feature, W0, b0);
    k_l0stats<<<1184, BLK>>>(gidx);
    k_fin0<<<1, 64>>>(g0, be0);
    k_layer1<<<1184, BLK, SM1>>>(gidx, W1, b1);
    k_fin1<<<1, 64>>>(g1, be1);
    k_layer2<<<1184, BLK, SM2>>>(W2, b2);
    k_fin2<<<1, 128>>>(g2, be2);
    k_poolapply<<<5000, BLK>>>(featBase);
}